// round 3
// baseline (speedup 1.0000x reference)
#include <cuda_runtime.h>
#include <cuda_bf16.h>
#include <cstdint>
#include <cstddef>

typedef unsigned int u32;

#define BN 4
#define TT 2048
#define CC 1024
#define MROWS (BN*TT)   // 8192

// ======================= device scratch (no allocs allowed) =======================
__device__ __align__(256) __nv_bfloat16 g_xh[MROWS*CC];
__device__ __align__(256) __nv_bfloat16 g_xl[MROWS*CC];
__device__ __align__(256) __nv_bfloat16 g_wh[4*CC*CC];
__device__ __align__(256) __nv_bfloat16 g_wl[4*CC*CC];
__device__ __align__(256) __nv_bfloat16 g_qh[MROWS*CC];
__device__ __align__(256) __nv_bfloat16 g_ql[MROWS*CC];
__device__ __align__(256) __nv_bfloat16 g_kh[MROWS*CC];
__device__ __align__(256) __nv_bfloat16 g_kl[MROWS*CC];
__device__ __align__(256) __nv_bfloat16 g_vth[MROWS*CC];  // V^T: [b][d][s]
__device__ __align__(256) __nv_bfloat16 g_vtl[MROWS*CC];
__device__ __align__(256) float         g_s [(size_t)BN*TT*TT];
__device__ __align__(256) __nv_bfloat16 g_ph[(size_t)BN*TT*TT];
__device__ __align__(256) __nv_bfloat16 g_pl[(size_t)BN*TT*TT];
__device__ __align__(256) __nv_bfloat16 g_ch[MROWS*CC];
__device__ __align__(256) __nv_bfloat16 g_cl[MROWS*CC];

// ======================= PTX helpers (sm_100 baseline, NO 'a' features) =======================
__device__ __forceinline__ u32 smem_u32(const void* p) {
    u32 a;
    asm("{ .reg .u64 t; cvta.to.shared.u64 t, %1; cvt.u32.u64 %0, t; }" : "=r"(a) : "l"(p));
    return a;
}
__device__ __forceinline__ void cpa16(u32 dst, const void* src) {
    asm volatile("cp.async.cg.shared.global [%0], [%1], 16;" :: "r"(dst), "l"(src) : "memory");
}
#define CP_COMMIT() asm volatile("cp.async.commit_group;" ::: "memory")
#define CP_WAIT(n)  asm volatile("cp.async.wait_group %0;" :: "n"(n) : "memory")

#define LDSM4(d0,d1,d2,d3,a) \
    asm volatile("ldmatrix.sync.aligned.m8n8.x4.shared.b16 {%0,%1,%2,%3}, [%4];" \
                 : "=r"(d0),"=r"(d1),"=r"(d2),"=r"(d3) : "r"(a))
#define LDSM2(d0,d1,a) \
    asm volatile("ldmatrix.sync.aligned.m8n8.x2.shared.b16 {%0,%1}, [%2];" \
                 : "=r"(d0),"=r"(d1) : "r"(a))

__device__ __forceinline__ void mma16816(float* c, const u32* a, const u32* b) {
    asm volatile(
        "mma.sync.aligned.m16n8k16.row.col.f32.bf16.bf16.f32 "
        "{%0,%1,%2,%3}, {%4,%5,%6,%7}, {%8,%9}, {%0,%1,%2,%3};"
        : "+f"(c[0]), "+f"(c[1]), "+f"(c[2]), "+f"(c[3])
        : "r"(a[0]), "r"(a[1]), "r"(a[2]), "r"(a[3]), "r"(b[0]), "r"(b[1]));
}

__device__ __forceinline__ u32 pack_bf2(__nv_bfloat16 a, __nv_bfloat16 b) {
    __nv_bfloat162 t = __halves2bfloat162(a, b);
    return *reinterpret_cast<u32*>(&t);
}
__device__ __forceinline__ unsigned short bf_bits(__nv_bfloat16 h) {
    return *reinterpret_cast<unsigned short*>(&h);
}

// ======================= GEMM kernel =======================
// stage: Ah(16K) Al(16K) Bh(16K) Bl(16K) = 64KB; 2 stages
#define ST_BYTES   65536u
#define SMEM_BYTES (1024 + 2*65536)

// MODE 0: split bf16 hi/lo row-major (+optional bias, +batch stride on C)
// MODE 1: V-projection: bias then transposed split store into vt[b][d][s]
// MODE 2: fp32 * scale row-major (+batch stride on C)
// MODE 3: fp32 + bias row-major (final output)
template<int MODE>
__global__ void __launch_bounds__(256, 1) gemm_bf16x3(
    const __nv_bfloat16* __restrict__ Ah, const __nv_bfloat16* __restrict__ Al,
    const __nv_bfloat16* __restrict__ Bh, const __nv_bfloat16* __restrict__ Bl,
    int lda, int ldb, int K,
    long long sAz, long long sBz, long long sCz,
    const float* __restrict__ bias, float scale,
    __nv_bfloat16* __restrict__ outH, __nv_bfloat16* __restrict__ outL,
    float* __restrict__ outF, int ldc)
{
    extern __shared__ __align__(1024) char smem_raw[];
    const u32 sb0 = smem_u32(smem_raw);
    const u32 sb  = (sb0 + 1023u) & ~1023u;
    char* smem_ptr = smem_raw + (sb - sb0);

    const int tid  = threadIdx.x;
    const int lane = tid & 31, wid = tid >> 5;
    const int wm = wid & 1, wn = wid >> 1;          // 2 x 4 warp grid
    const int m0 = blockIdx.x * 128, n0 = blockIdx.y * 128;
    const long long z = blockIdx.z;
    Ah += z * sAz; Al += z * sAz; Bh += z * sBz; Bl += z * sBz;

    float acc[4][4][4];
    #pragma unroll
    for (int i = 0; i < 4; ++i)
        #pragma unroll
        for (int j = 0; j < 4; ++j)
            #pragma unroll
            for (int e = 0; e < 4; ++e) acc[i][j][e] = 0.f;

    // ---- cp.async loader: thread t -> row t/2, 4x16B chunks at (t&1)*4 ----
    const int r  = tid >> 1;
    const int c0 = (tid & 1) * 4;
    const __nv_bfloat16* gAh = Ah + (size_t)(m0 + r) * lda + c0 * 8;
    const __nv_bfloat16* gAl = Al + (size_t)(m0 + r) * lda + c0 * 8;
    const __nv_bfloat16* gBh = Bh + (size_t)(n0 + r) * ldb + c0 * 8;
    const __nv_bfloat16* gBl = Bl + (size_t)(n0 + r) * ldb + c0 * 8;
    u32 swoff[4];
    #pragma unroll
    for (int j = 0; j < 4; ++j) {
        u32 c16 = (u32)(c0 + j);
        swoff[j] = (u32)r * 128u + ((c16 ^ ((u32)r & 7u)) << 4);
    }

    auto load_stage = [&](int s, int k0) {
        const u32 b = sb + (u32)s * ST_BYTES;
        #pragma unroll
        for (int j = 0; j < 4; ++j) {
            const u32 dst = b + swoff[j];
            cpa16(dst,           gAh + k0 + j * 8);
            cpa16(dst + 16384u,  gAl + k0 + j * 8);
            cpa16(dst + 32768u,  gBh + k0 + j * 8);
            cpa16(dst + 49152u,  gBl + k0 + j * 8);
        }
        CP_COMMIT();
    };

    const int nch = K >> 6;
    load_stage(0, 0);
    if (nch > 1) load_stage(1, 64);

    const int rA = lane & 15, cA = lane >> 4;          // ldmatrix x4 lane map (A)
    const int rB = lane & 7,  cB = (lane >> 3) & 1;    // ldmatrix x2 lane map (B)

    for (int c = 0; c < nch; ++c) {
        if (c + 1 < nch) { CP_WAIT(1); } else { CP_WAIT(0); }
        __syncthreads();
        const u32 base = sb + (u32)(c & 1) * ST_BYTES;

        #pragma unroll
        for (int ks = 0; ks < 4; ++ks) {
            u32 ah[4][4], al[4][4], bh[4][2], bl[4][2];
            #pragma unroll
            for (int am = 0; am < 4; ++am) {
                const int row = wm * 64 + am * 16 + rA;
                const u32 a = base + (u32)row * 128u
                            + ((u32)((ks * 2 + cA) ^ (row & 7)) << 4);
                LDSM4(ah[am][0], ah[am][1], ah[am][2], ah[am][3], a);
                LDSM4(al[am][0], al[am][1], al[am][2], al[am][3], a + 16384u);
            }
            #pragma unroll
            for (int bn = 0; bn < 4; ++bn) {
                const int row = wn * 32 + bn * 8 + rB;
                const u32 a = base + 32768u + (u32)row * 128u
                            + ((u32)((ks * 2 + cB) ^ (row & 7)) << 4);
                LDSM2(bh[bn][0], bh[bn][1], a);
                LDSM2(bl[bn][0], bl[bn][1], a + 16384u);
            }
            #pragma unroll
            for (int am = 0; am < 4; ++am)
                #pragma unroll
                for (int bn = 0; bn < 4; ++bn) {
                    mma16816(acc[am][bn], ah[am], bh[bn]);
                    mma16816(acc[am][bn], ah[am], bl[bn]);
                    mma16816(acc[am][bn], al[am], bh[bn]);
                }
        }
        __syncthreads();
        if (c + 2 < nch) load_stage(c & 1, (c + 2) * 64);
    }

    // ======================= epilogue =======================
    const int q = lane >> 2, tq = lane & 3;

    if (MODE == 1) {
        // transpose 128x128 tile through smem (u32 = packed hi|lo), stride 132
        u32* T = reinterpret_cast<u32*>(smem_ptr);
        #pragma unroll
        for (int am = 0; am < 4; ++am)
            #pragma unroll
            for (int bn = 0; bn < 4; ++bn)
                #pragma unroll
                for (int e = 0; e < 4; ++e) {
                    const int ml = wm * 64 + am * 16 + q + (e >> 1) * 8;
                    const int nl = wn * 32 + bn * 8 + 2 * tq + (e & 1);
                    const float v = acc[am][bn][e] + bias[n0 + nl];
                    const __nv_bfloat16 h = __float2bfloat16(v);
                    const __nv_bfloat16 l = __float2bfloat16(v - __bfloat162float(h));
                    T[nl * 132 + ml] = ((u32)bf_bits(l) << 16) | (u32)bf_bits(h);
                }
        __syncthreads();
        const int d  = tid >> 1;
        const int mh = (tid & 1) * 64;
        const int b  = m0 >> 11;
        const size_t idx = ((size_t)b * CC + (n0 + d)) * TT + (m0 & 2047) + mh;
        #pragma unroll
        for (int i = 0; i < 64; i += 8) {
            u32 hw[4], lw[4];
            #pragma unroll
            for (int p = 0; p < 4; ++p) {
                const u32 t0 = T[d * 132 + mh + i + 2 * p];
                const u32 t1 = T[d * 132 + mh + i + 2 * p + 1];
                hw[p] = (t0 & 0xffffu) | (t1 << 16);
                lw[p] = (t0 >> 16)     | (t1 & 0xffff0000u);
            }
            *reinterpret_cast<uint4*>(outH + idx + i) = make_uint4(hw[0], hw[1], hw[2], hw[3]);
            *reinterpret_cast<uint4*>(outL + idx + i) = make_uint4(lw[0], lw[1], lw[2], lw[3]);
        }
        return;
    }

    if (MODE == 0) { outH += z * sCz; outL += z * sCz; }
    else           { outF += z * sCz; }

    #pragma unroll
    for (int am = 0; am < 4; ++am)
        #pragma unroll
        for (int e2 = 0; e2 < 2; ++e2) {
            const int gm = m0 + wm * 64 + am * 16 + q + e2 * 8;
            #pragma unroll
            for (int bn = 0; bn < 4; ++bn) {
                const int gn = n0 + wn * 32 + bn * 8 + 2 * tq;
                float v0 = acc[am][bn][e2 * 2 + 0];
                float v1 = acc[am][bn][e2 * 2 + 1];
                if (MODE == 0) {
                    if (bias) { v0 += bias[gn]; v1 += bias[gn + 1]; }
                    const __nv_bfloat16 h0 = __float2bfloat16(v0), h1 = __float2bfloat16(v1);
                    const __nv_bfloat16 l0 = __float2bfloat16(v0 - __bfloat162float(h0));
                    const __nv_bfloat16 l1 = __float2bfloat16(v1 - __bfloat162float(h1));
                    *reinterpret_cast<u32*>(outH + (size_t)gm * ldc + gn) = pack_bf2(h0, h1);
                    *reinterpret_cast<u32*>(outL + (size_t)gm * ldc + gn) = pack_bf2(l0, l1);
                } else if (MODE == 2) {
                    float2 val; val.x = v0 * scale; val.y = v1 * scale;
                    *reinterpret_cast<float2*>(outF + (size_t)gm * ldc + gn) = val;
                } else {
                    float2 val; val.x = v0 + bias[gn]; val.y = v1 + bias[gn + 1];
                    *reinterpret_cast<float2*>(outF + (size_t)gm * ldc + gn) = val;
                }
            }
        }
}

// ======================= split fp32 -> bf16 hi/lo =======================
__global__ void __launch_bounds__(256) split_kernel(
    const float* __restrict__ x, __nv_bfloat16* __restrict__ h,
    __nv_bfloat16* __restrict__ l, int n4)
{
    int i = blockIdx.x * 256 + threadIdx.x;
    if (i >= n4) return;
    float4 v = reinterpret_cast<const float4*>(x)[i];
    float vv[4] = { v.x, v.y, v.z, v.w };
    __nv_bfloat16 hh[4], ll[4];
    #pragma unroll
    for (int c = 0; c < 4; ++c) {
        hh[c] = __float2bfloat16(vv[c]);
        ll[c] = __float2bfloat16(vv[c] - __bfloat162float(hh[c]));
    }
    *reinterpret_cast<uint2*>(h + 4*(size_t)i) = make_uint2(pack_bf2(hh[0],hh[1]), pack_bf2(hh[2],hh[3]));
    *reinterpret_cast<uint2*>(l + 4*(size_t)i) = make_uint2(pack_bf2(ll[0],ll[1]), pack_bf2(ll[2],ll[3]));
}

// ======================= softmax + split =======================
__global__ void __launch_bounds__(256) softmax_split_kernel(
    const float* __restrict__ S, __nv_bfloat16* __restrict__ Ph, __nv_bfloat16* __restrict__ Pl)
{
    __shared__ float red[8];
    __shared__ float sM, sInv;
    const size_t row = blockIdx.x;
    const float4* src = reinterpret_cast<const float4*>(S + row * TT);
    const int t = threadIdx.x, w = t >> 5, ln = t & 31;

    float4 a = src[t], b2 = src[t + 256];
    float mx = fmaxf(fmaxf(fmaxf(a.x, a.y), fmaxf(a.z, a.w)),
                     fmaxf(fmaxf(b2.x, b2.y), fmaxf(b2.z, b2.w)));
    #pragma unroll
    for (int o = 16; o; o >>= 1) mx = fmaxf(mx, __shfl_xor_sync(0xffffffffu, mx, o));
    if (ln == 0) red[w] = mx;
    __syncthreads();
    if (t == 0) {
        float m = red[0];
        #pragma unroll
        for (int i = 1; i < 8; ++i) m = fmaxf(m, red[i]);
        sM = m;
    }
    __syncthreads();
    const float M = sM;

    float e[8];
    e[0] = __expf(a.x - M);  e[1] = __expf(a.y - M);
    e[2] = __expf(a.z - M);  e[3] = __expf(a.w - M);
    e[4] = __expf(b2.x - M); e[5] = __expf(b2.y - M);
    e[6] = __expf(b2.z - M); e[7] = __expf(b2.w - M);
    float sm = e[0]+e[1]+e[2]+e[3]+e[4]+e[5]+e[6]+e[7];
    #pragma unroll
    for (int o = 16; o; o >>= 1) sm += __shfl_xor_sync(0xffffffffu, sm, o);
    __syncthreads();
    if (ln == 0) red[w] = sm;
    __syncthreads();
    if (t == 0) {
        float ssum = 0.f;
        #pragma unroll
        for (int i = 0; i < 8; ++i) ssum += red[i];
        sInv = 1.0f / ssum;
    }
    __syncthreads();
    const float inv = sInv;

    #pragma unroll
    for (int half = 0; half < 2; ++half) {
        __nv_bfloat16 hh[4], ll[4];
        #pragma unroll
        for (int c = 0; c < 4; ++c) {
            float p = e[half*4 + c] * inv;
            hh[c] = __float2bfloat16(p);
            ll[c] = __float2bfloat16(p - __bfloat162float(hh[c]));
        }
        size_t off = row * TT + (size_t)(t + half*256) * 4;
        *reinterpret_cast<uint2*>(Ph + off) = make_uint2(pack_bf2(hh[0],hh[1]), pack_bf2(hh[2],hh[3]));
        *reinterpret_cast<uint2*>(Pl + off) = make_uint2(pack_bf2(ll[0],ll[1]), pack_bf2(ll[2],ll[3]));
    }
}

// ======================= host launch =======================
static void* sym_addr(const void* s) {
    void* p = nullptr;
    cudaGetSymbolAddress(&p, s);
    return p;
}

extern "C" void kernel_launch(void* const* d_in, const int* in_sizes, int n_in,
                              void* d_out, int out_size) {
    (void)in_sizes; (void)n_in; (void)out_size;
    const float* x  = (const float*)d_in[0];
    const float* Wq = (const float*)d_in[1];
    const float* bq = (const float*)d_in[2];
    const float* Wk = (const float*)d_in[3];
    const float* bk = (const float*)d_in[4];
    const float* Wv = (const float*)d_in[5];
    const float* bv = (const float*)d_in[6];
    const float* Wo = (const float*)d_in[7];
    const float* bo = (const float*)d_in[8];
    float* out = (float*)d_out;

    __nv_bfloat16* xh  = (__nv_bfloat16*)sym_addr(g_xh);
    __nv_bfloat16* xl  = (__nv_bfloat16*)sym_addr(g_xl);
    __nv_bfloat16* wh  = (__nv_bfloat16*)sym_addr(g_wh);
    __nv_bfloat16* wl  = (__nv_bfloat16*)sym_addr(g_wl);
    __nv_bfloat16* qh  = (__nv_bfloat16*)sym_addr(g_qh);
    __nv_bfloat16* ql  = (__nv_bfloat16*)sym_addr(g_ql);
    __nv_bfloat16* kh  = (__nv_bfloat16*)sym_addr(g_kh);
    __nv_bfloat16* kl  = (__nv_bfloat16*)sym_addr(g_kl);
    __nv_bfloat16* vth = (__nv_bfloat16*)sym_addr(g_vth);
    __nv_bfloat16* vtl = (__nv_bfloat16*)sym_addr(g_vtl);
    float*         sS  = (float*)sym_addr(g_s);
    __nv_bfloat16* ph  = (__nv_bfloat16*)sym_addr(g_ph);
    __nv_bfloat16* pl  = (__nv_bfloat16*)sym_addr(g_pl);
    __nv_bfloat16* ch  = (__nv_bfloat16*)sym_addr(g_ch);
    __nv_bfloat16* cl  = (__nv_bfloat16*)sym_addr(g_cl);

    cudaFuncSetAttribute(gemm_bf16x3<0>, cudaFuncAttributeMaxDynamicSharedMemorySize, SMEM_BYTES);
    cudaFuncSetAttribute(gemm_bf16x3<1>, cudaFuncAttributeMaxDynamicSharedMemorySize, SMEM_BYTES);
    cudaFuncSetAttribute(gemm_bf16x3<2>, cudaFuncAttributeMaxDynamicSharedMemorySize, SMEM_BYTES);
    cudaFuncSetAttribute(gemm_bf16x3<3>, cudaFuncAttributeMaxDynamicSharedMemorySize, SMEM_BYTES);

    // splits
    split_kernel<<<(MROWS*CC/4 + 255)/256, 256>>>(x,  xh, xl, MROWS*CC/4);
    split_kernel<<<(CC*CC/4 + 255)/256, 256>>>(Wq, wh + 0*(size_t)CC*CC, wl + 0*(size_t)CC*CC, CC*CC/4);
    split_kernel<<<(CC*CC/4 + 255)/256, 256>>>(Wk, wh + 1*(size_t)CC*CC, wl + 1*(size_t)CC*CC, CC*CC/4);
    split_kernel<<<(CC*CC/4 + 255)/256, 256>>>(Wv, wh + 2*(size_t)CC*CC, wl + 2*(size_t)CC*CC, CC*CC/4);
    split_kernel<<<(CC*CC/4 + 255)/256, 256>>>(Wo, wh + 3*(size_t)CC*CC, wl + 3*(size_t)CC*CC, CC*CC/4);

    dim3 gProj(MROWS/128, CC/128, 1);     // (64, 8, 1)
    // Q = x Wq^T + bq
    gemm_bf16x3<0><<<gProj, 256, SMEM_BYTES>>>(xh, xl, wh + 0*(size_t)CC*CC, wl + 0*(size_t)CC*CC,
        CC, CC, CC, 0, 0, 0, bq, 1.f, qh, ql, nullptr, CC);
    // K
    gemm_bf16x3<0><<<gProj, 256, SMEM_BYTES>>>(xh, xl, wh + 1*(size_t)CC*CC, wl + 1*(size_t)CC*CC,
        CC, CC, CC, 0, 0, 0, bk, 1.f, kh, kl, nullptr, CC);
    // V -> transposed store vt[b][d][s]
    gemm_bf16x3<1><<<gProj, 256, SMEM_BYTES>>>(xh, xl, wh + 2*(size_t)CC*CC, wl + 2*(size_t)CC*CC,
        CC, CC, CC, 0, 0, 0, bv, 1.f, vth, vtl, nullptr, 0);

    // scores = Q K^T / 32  (per batch)
    dim3 gScore(TT/128, TT/128, BN);      // (16, 16, 4)
    gemm_bf16x3<2><<<gScore, 256, SMEM_BYTES>>>(qh, ql, kh, kl,
        CC, CC, CC, (long long)TT*CC, (long long)TT*CC, (long long)TT*TT,
        nullptr, 0.03125f, nullptr, nullptr, sS, TT);

    // softmax + split
    softmax_split_kernel<<<MROWS, 256>>>(sS, ph, pl);

    // ctx = P V  (A = P [t][s], B = vt [d][s], per batch)
    dim3 gPV(TT/128, CC/128, BN);         // (16, 8, 4)
    gemm_bf16x3<0><<<gPV, 256, SMEM_BYTES>>>(ph, pl, vth, vtl,
        TT, TT, TT, (long long)TT*TT, (long long)CC*TT, (long long)TT*CC,
        nullptr, 1.f, ch, cl, nullptr, CC);

    // out = ctx Wo^T + bo  (fp32 -> d_out)
    gemm_bf16x3<3><<<gProj, 256, SMEM_BYTES>>>(ch, cl, wh + 3*(size_t)CC*CC, wl + 3*(size_t)CC*CC,
        CC, CC, CC, 0, 0, 0, bo, 1.f, nullptr, nullptr, out, CC);
}